// round 3
// baseline (speedup 1.0000x reference)
#include <cuda_runtime.h>
#include <cstdint>

// Problem constants (fixed dataset: N=100000, E=3200000, D=128)
#define MAXN 100000
#define MAXE 3200000
#define D 128

__device__ float g_H1[(size_t)MAXN * D];        // 51.2 MB ping
__device__ float g_H2[(size_t)MAXN * D];        // 51.2 MB pong
__device__ int   g_deg[MAXN];
__device__ float g_dis[MAXN];
__device__ int   g_rp[MAXN + 1];
__device__ int   g_cur[MAXN];
__device__ int   g_ci[MAXE + MAXN];             // CSR col indices (edges + self loops)
__device__ float g_w[MAXE + MAXN];              // per-entry normalized weight
__device__ int   g_is64;                        // 1 if edge dtype is int64

// Fetch element e of the edge buffer honoring detected dtype.
__device__ __forceinline__ int edge_at(const void* p, long long e, int is64) {
    if (is64) return (int)((const long long*)p)[e];
    return ((const int*)p)[e];
}

// ---------------------------------------------------------------------------
// 0) dtype detector: int64 LE with values < 2^31 has zero high words at odd
//    int32 positions. 128 consecutive zeros from random int32 data: ~impossible.
// ---------------------------------------------------------------------------
__global__ void detect_kernel(const int* __restrict__ buf) {
    if (threadIdx.x == 0 && blockIdx.x == 0) {
        int allzero = 1;
        #pragma unroll 1
        for (int k = 0; k < 128; k++) {
            if (buf[2 * k + 1] != 0) { allzero = 0; break; }
        }
        g_is64 = allzero;
    }
}

// ---------------------------------------------------------------------------
// 1) deg[i] = 1 (self loop) ; then histogram over edge rows
// ---------------------------------------------------------------------------
__global__ void init_deg_kernel(int N) {
    int i = blockIdx.x * blockDim.x + threadIdx.x;
    if (i < N) g_deg[i] = 1;
}

__global__ void hist_kernel(const void* __restrict__ ebuf, int E, int N) {
    int e = blockIdx.x * blockDim.x + threadIdx.x;
    if (e < E) {
        int r = edge_at(ebuf, e, g_is64);           // rows = elements [0, E)
        if ((unsigned)r < (unsigned)N) atomicAdd(&g_deg[r], 1);
    }
}

// ---------------------------------------------------------------------------
// 2) exclusive scan of deg -> row_ptr (single block, chunked shared-mem scan)
// ---------------------------------------------------------------------------
__global__ void scan_kernel(int N) {
    __shared__ int sh[1024];
    __shared__ int carry_s;
    int tid = threadIdx.x;
    if (tid == 0) { carry_s = 0; g_rp[0] = 0; }
    __syncthreads();
    for (int base = 0; base < N; base += 1024) {
        int i = base + tid;
        int v = (i < N) ? g_deg[i] : 0;
        sh[tid] = v;
        __syncthreads();
        for (int off = 1; off < 1024; off <<= 1) {
            int t = (tid >= off) ? sh[tid - off] : 0;
            __syncthreads();
            sh[tid] += t;
            __syncthreads();
        }
        int carry = carry_s;
        if (i < N) g_rp[i + 1] = carry + sh[tid];
        __syncthreads();
        if (tid == 1023) carry_s = carry + sh[1023];
        __syncthreads();
    }
}

// ---------------------------------------------------------------------------
// 3) dis[i] = rsqrt(deg[i]) ; cursor init for counting-sort scatter
// ---------------------------------------------------------------------------
__global__ void prep_kernel(int N) {
    int i = blockIdx.x * blockDim.x + threadIdx.x;
    if (i < N) {
        g_dis[i] = rsqrtf((float)g_deg[i]);   // deg >= 1 always (self loop)
        g_cur[i] = g_rp[i];
    }
}

// ---------------------------------------------------------------------------
// 4) scatter edges (+self loops) into CSR, computing w = dis[r]*dis[c]
//    rows = ebuf[idx], cols = ebuf[E + idx]
// ---------------------------------------------------------------------------
__global__ void scatter_kernel(const void* __restrict__ ebuf, int E, int N) {
    int idx = blockIdx.x * blockDim.x + threadIdx.x;
    int total = E + N;
    if (idx >= total) return;
    int is64 = g_is64;
    int r, c;
    if (idx < E) {
        r = edge_at(ebuf, idx, is64);
        c = edge_at(ebuf, (long long)E + idx, is64);
        if ((unsigned)r >= (unsigned)N || (unsigned)c >= (unsigned)N) return;
    } else {
        r = idx - E; c = r;
    }
    int pos = atomicAdd(&g_cur[r], 1);
    if ((unsigned)pos < (unsigned)(MAXE + MAXN)) {
        g_ci[pos] = c;
        g_w[pos]  = g_dis[r] * g_dis[c];
    }
}

// ---------------------------------------------------------------------------
// 5) SPMM: one warp per row, lane owns 4 contiguous feature cols (float4).
//    4-way unrolled gather loop for memory-level parallelism on L2 hits.
//    mode 0: ext -> g_H1 ; mode 1: g_H1 -> g_H2 ; mode 2: g_H2 -> ext
// ---------------------------------------------------------------------------
__global__ void spmm_kernel(int mode, const float* __restrict__ hin_ext,
                            float* __restrict__ hout_ext, int N) {
    int warp = (blockIdx.x * blockDim.x + threadIdx.x) >> 5;
    int lane = threadIdx.x & 31;
    if (warp >= N) return;

    const float* Hin  = (mode == 0) ? hin_ext : (mode == 1 ? g_H1 : g_H2);
    float*       Hout = (mode == 0) ? g_H1    : (mode == 1 ? g_H2 : hout_ext);

    int s = g_rp[warp];
    int e = g_rp[warp + 1];
    int off = lane * 4;

    float4 acc = make_float4(0.f, 0.f, 0.f, 0.f);
    int j = s;
    // 4-way unroll: 4 independent 128B row gathers in flight per warp
    for (; j + 3 < e; j += 4) {
        int   c0 = __ldg(&g_ci[j]);
        int   c1 = __ldg(&g_ci[j + 1]);
        int   c2 = __ldg(&g_ci[j + 2]);
        int   c3 = __ldg(&g_ci[j + 3]);
        float w0 = __ldg(&g_w[j]);
        float w1 = __ldg(&g_w[j + 1]);
        float w2 = __ldg(&g_w[j + 2]);
        float w3 = __ldg(&g_w[j + 3]);
        float4 h0 = *reinterpret_cast<const float4*>(Hin + (size_t)c0 * D + off);
        float4 h1 = *reinterpret_cast<const float4*>(Hin + (size_t)c1 * D + off);
        float4 h2 = *reinterpret_cast<const float4*>(Hin + (size_t)c2 * D + off);
        float4 h3 = *reinterpret_cast<const float4*>(Hin + (size_t)c3 * D + off);
        acc.x += w0 * h0.x; acc.y += w0 * h0.y; acc.z += w0 * h0.z; acc.w += w0 * h0.w;
        acc.x += w1 * h1.x; acc.y += w1 * h1.y; acc.z += w1 * h1.z; acc.w += w1 * h1.w;
        acc.x += w2 * h2.x; acc.y += w2 * h2.y; acc.z += w2 * h2.z; acc.w += w2 * h2.w;
        acc.x += w3 * h3.x; acc.y += w3 * h3.y; acc.z += w3 * h3.z; acc.w += w3 * h3.w;
    }
    for (; j < e; j++) {
        int   c0 = __ldg(&g_ci[j]);
        float w0 = __ldg(&g_w[j]);
        float4 h0 = *reinterpret_cast<const float4*>(Hin + (size_t)c0 * D + off);
        acc.x += w0 * h0.x; acc.y += w0 * h0.y; acc.z += w0 * h0.z; acc.w += w0 * h0.w;
    }
    *reinterpret_cast<float4*>(Hout + (size_t)warp * D + off) = acc;
}

// ---------------------------------------------------------------------------
extern "C" void kernel_launch(void* const* d_in, const int* in_sizes, int n_in,
                              void* d_out, int out_size) {
    const float* h  = (const float*)d_in[0];
    const void*  ei = d_in[1];

    int N = in_sizes[0] / D;      // 100000
    int E = in_sizes[1] / 2;      // 3200000 (element count, dtype-agnostic)

    const int TB = 256;
    int gN = (N + TB - 1) / TB;
    int gE = (E + TB - 1) / TB;
    int gS = (E + N + TB - 1) / TB;

    detect_kernel<<<1, 32>>>((const int*)ei);
    init_deg_kernel<<<gN, TB>>>(N);
    hist_kernel<<<gE, TB>>>(ei, E, N);
    scan_kernel<<<1, 1024>>>(N);
    prep_kernel<<<gN, TB>>>(N);
    scatter_kernel<<<gS, TB>>>(ei, E, N);

    int gW = (N + 7) / 8;   // warp per row, 8 warps/block
    spmm_kernel<<<gW, TB>>>(0, h, nullptr, N);
    spmm_kernel<<<gW, TB>>>(1, nullptr, nullptr, N);
    spmm_kernel<<<gW, TB>>>(2, nullptr, (float*)d_out, N);
}

// round 6
// speedup vs baseline: 1.3101x; 1.3101x over previous
#include <cuda_runtime.h>
#include <cstdint>

// Problem constants (fixed dataset: N=100000, E=3200000, D=128)
#define MAXN 100000
#define MAXE 3200000
#define D 128
#define SCAN_TB 1024
#define MAX_BLOCKS ((MAXN + SCAN_TB - 1) / SCAN_TB)   // 98

__device__ float g_H1[(size_t)MAXN * D];        // 51.2 MB ping
__device__ float g_H2[(size_t)MAXN * D];        // 51.2 MB pong
__device__ int   g_deg[MAXN];
__device__ float g_dis[MAXN];
__device__ int   g_rp[MAXN + 1];
__device__ int   g_cur[MAXN];
__device__ int   g_bsum[MAX_BLOCKS];            // per-block sums for 2-level scan
__device__ int   g_boff[MAX_BLOCKS];            // scanned (exclusive) block offsets
__device__ int   g_ci[MAXE + MAXN];             // CSR col indices (edges + self loops)
__device__ float g_w[MAXE + MAXN];              // per-entry normalized weight
__device__ int   g_is64;                        // 1 if edge dtype is int64

// Fetch element e of the edge buffer honoring detected dtype.
__device__ __forceinline__ int edge_at(const void* p, long long e, int is64) {
    if (is64) return (int)((const long long*)p)[e];
    return ((const int*)p)[e];
}

// ---------------------------------------------------------------------------
// 0) dtype detector: int64 LE with values < 2^31 has zero high words at odd
//    int32 positions. 128 consecutive zeros from random int32 data: ~impossible.
// ---------------------------------------------------------------------------
__global__ void detect_kernel(const int* __restrict__ buf) {
    if (threadIdx.x == 0 && blockIdx.x == 0) {
        int allzero = 1;
        #pragma unroll 1
        for (int k = 0; k < 128; k++) {
            if (buf[2 * k + 1] != 0) { allzero = 0; break; }
        }
        g_is64 = allzero;
    }
}

// ---------------------------------------------------------------------------
// 1) deg[i] = 1 (self loop) ; then histogram over edge rows
// ---------------------------------------------------------------------------
__global__ void init_deg_kernel(int N) {
    int i = blockIdx.x * blockDim.x + threadIdx.x;
    if (i < N) g_deg[i] = 1;
}

__global__ void hist_kernel(const void* __restrict__ ebuf, int E, int N) {
    int e = blockIdx.x * blockDim.x + threadIdx.x;
    if (e < E) {
        int r = edge_at(ebuf, e, g_is64);           // rows = elements [0, E)
        if ((unsigned)r < (unsigned)N) atomicAdd(&g_deg[r], 1);
    }
}

// ---------------------------------------------------------------------------
// 2a) per-block inclusive scan (warp shuffle), partials -> g_rp[i+1],
//     block total -> g_bsum[blockIdx]
// ---------------------------------------------------------------------------
__global__ void scan_blocks_kernel(int N) {
    __shared__ int warp_sums[32];
    int tid  = threadIdx.x;
    int lane = tid & 31;
    int wid  = tid >> 5;
    int i    = blockIdx.x * SCAN_TB + tid;

    int v = (i < N) ? g_deg[i] : 0;

    // intra-warp inclusive scan
    int x = v;
    #pragma unroll
    for (int off = 1; off < 32; off <<= 1) {
        int t = __shfl_up_sync(0xFFFFFFFFu, x, off);
        if (lane >= off) x += t;
    }
    if (lane == 31) warp_sums[wid] = x;
    __syncthreads();

    // warp 0 scans the 32 warp sums
    if (wid == 0) {
        int s = warp_sums[lane];
        #pragma unroll
        for (int off = 1; off < 32; off <<= 1) {
            int t = __shfl_up_sync(0xFFFFFFFFu, s, off);
            if (lane >= off) s += t;
        }
        warp_sums[lane] = s;
    }
    __syncthreads();

    int base = (wid > 0) ? warp_sums[wid - 1] : 0;
    int incl = base + x;                    // inclusive within block
    if (i < N) g_rp[i + 1] = incl;          // partial; fixed up in phase 3
    if (tid == SCAN_TB - 1) g_bsum[blockIdx.x] = incl;
}

// ---------------------------------------------------------------------------
// 2b) single small block scans the block sums -> exclusive offsets g_boff
// ---------------------------------------------------------------------------
__global__ void scan_bsum_kernel(int nblocks) {
    // nblocks <= 128: scan with a 128-thread block (4 warps, shared relay)
    __shared__ int ws[4];
    int tid  = threadIdx.x;
    int lane = tid & 31;
    int wid  = tid >> 5;
    int v = (tid < nblocks) ? g_bsum[tid] : 0;
    int x = v;
    #pragma unroll
    for (int off = 1; off < 32; off <<= 1) {
        int t = __shfl_up_sync(0xFFFFFFFFu, x, off);
        if (lane >= off) x += t;
    }
    if (lane == 31) ws[wid] = x;
    __syncthreads();
    if (wid == 0 && lane < 4) {
        int s = ws[lane];
        #pragma unroll
        for (int off = 1; off < 4; off <<= 1) {
            int t = __shfl_up_sync(0xFu, s, off);
            if (lane >= off) s += t;
        }
        ws[lane] = s;
    }
    __syncthreads();
    int base = (wid > 0) ? ws[wid - 1] : 0;
    if (tid < nblocks) g_boff[tid] = base + x - v;   // exclusive offset
    if (tid == 0) g_rp[0] = 0;
}

// ---------------------------------------------------------------------------
// 2c) fixup + prep fused: finalize rp[i+1], derive cur[i] (= exclusive prefix)
//     and dis[i] without any cross-thread dependency.
// ---------------------------------------------------------------------------
__global__ void scan_fixup_prep_kernel(int N) {
    int i = blockIdx.x * SCAN_TB + threadIdx.x;
    if (i < N) {
        int d    = g_deg[i];
        int incl = g_rp[i + 1] + g_boff[blockIdx.x];  // final inclusive prefix
        g_rp[i + 1] = incl;
        g_cur[i]    = incl - d;                        // final exclusive = rp[i]
        g_dis[i]    = rsqrtf((float)d);                // deg >= 1 (self loop)
    }
}

// ---------------------------------------------------------------------------
// 4) scatter edges (+self loops) into CSR, computing w = dis[r]*dis[c]
//    rows = ebuf[idx], cols = ebuf[E + idx]
// ---------------------------------------------------------------------------
__global__ void scatter_kernel(const void* __restrict__ ebuf, int E, int N) {
    int idx = blockIdx.x * blockDim.x + threadIdx.x;
    int total = E + N;
    if (idx >= total) return;
    int is64 = g_is64;
    int r, c;
    if (idx < E) {
        r = edge_at(ebuf, idx, is64);
        c = edge_at(ebuf, (long long)E + idx, is64);
        if ((unsigned)r >= (unsigned)N || (unsigned)c >= (unsigned)N) return;
    } else {
        r = idx - E; c = r;
    }
    int pos = atomicAdd(&g_cur[r], 1);
    if ((unsigned)pos < (unsigned)(MAXE + MAXN)) {
        g_ci[pos] = c;
        g_w[pos]  = g_dis[r] * g_dis[c];
    }
}

// ---------------------------------------------------------------------------
// 5) SPMM: one warp per row, lane owns 4 contiguous feature cols (float4).
//    4-way unrolled gather loop for memory-level parallelism on L2 hits.
//    mode 0: ext -> g_H1 ; mode 1: g_H1 -> g_H2 ; mode 2: g_H2 -> ext
// ---------------------------------------------------------------------------
__global__ void spmm_kernel(int mode, const float* __restrict__ hin_ext,
                            float* __restrict__ hout_ext, int N) {
    int warp = (blockIdx.x * blockDim.x + threadIdx.x) >> 5;
    int lane = threadIdx.x & 31;
    if (warp >= N) return;

    const float* Hin  = (mode == 0) ? hin_ext : (mode == 1 ? g_H1 : g_H2);
    float*       Hout = (mode == 0) ? g_H1    : (mode == 1 ? g_H2 : hout_ext);

    int s = g_rp[warp];
    int e = g_rp[warp + 1];
    int off = lane * 4;

    float4 acc = make_float4(0.f, 0.f, 0.f, 0.f);
    int j = s;
    // 4-way unroll: 4 independent 128B row gathers in flight per warp
    for (; j + 3 < e; j += 4) {
        int   c0 = __ldg(&g_ci[j]);
        int   c1 = __ldg(&g_ci[j + 1]);
        int   c2 = __ldg(&g_ci[j + 2]);
        int   c3 = __ldg(&g_ci[j + 3]);
        float w0 = __ldg(&g_w[j]);
        float w1 = __ldg(&g_w[j + 1]);
        float w2 = __ldg(&g_w[j + 2]);
        float w3 = __ldg(&g_w[j + 3]);
        float4 h0 = *reinterpret_cast<const float4*>(Hin + (size_t)c0 * D + off);
        float4 h1 = *reinterpret_cast<const float4*>(Hin + (size_t)c1 * D + off);
        float4 h2 = *reinterpret_cast<const float4*>(Hin + (size_t)c2 * D + off);
        float4 h3 = *reinterpret_cast<const float4*>(Hin + (size_t)c3 * D + off);
        acc.x += w0 * h0.x; acc.y += w0 * h0.y; acc.z += w0 * h0.z; acc.w += w0 * h0.w;
        acc.x += w1 * h1.x; acc.y += w1 * h1.y; acc.z += w1 * h1.z; acc.w += w1 * h1.w;
        acc.x += w2 * h2.x; acc.y += w2 * h2.y; acc.z += w2 * h2.z; acc.w += w2 * h2.w;
        acc.x += w3 * h3.x; acc.y += w3 * h3.y; acc.z += w3 * h3.z; acc.w += w3 * h3.w;
    }
    for (; j < e; j++) {
        int   c0 = __ldg(&g_ci[j]);
        float w0 = __ldg(&g_w[j]);
        float4 h0 = *reinterpret_cast<const float4*>(Hin + (size_t)c0 * D + off);
        acc.x += w0 * h0.x; acc.y += w0 * h0.y; acc.z += w0 * h0.z; acc.w += w0 * h0.w;
    }
    *reinterpret_cast<float4*>(Hout + (size_t)warp * D + off) = acc;
}

// ---------------------------------------------------------------------------
extern "C" void kernel_launch(void* const* d_in, const int* in_sizes, int n_in,
                              void* d_out, int out_size) {
    const float* h  = (const float*)d_in[0];
    const void*  ei = d_in[1];

    int N = in_sizes[0] / D;      // 100000
    int E = in_sizes[1] / 2;      // 3200000 (element count, dtype-agnostic)

    const int TB = 256;
    int gN = (N + TB - 1) / TB;
    int gE = (E + TB - 1) / TB;
    int gS = (E + N + TB - 1) / TB;
    int gScan = (N + SCAN_TB - 1) / SCAN_TB;    // 98

    detect_kernel<<<1, 32>>>((const int*)ei);
    init_deg_kernel<<<gN, TB>>>(N);
    hist_kernel<<<gE, TB>>>(ei, E, N);

    // 2-level parallel scan replacing the serial single-block scan
    scan_blocks_kernel<<<gScan, SCAN_TB>>>(N);
    scan_bsum_kernel<<<1, 128>>>(gScan);
    scan_fixup_prep_kernel<<<gScan, SCAN_TB>>>(N);

    scatter_kernel<<<gS, TB>>>(ei, E, N);

    int gW = (N + 7) / 8;   // warp per row, 8 warps/block
    spmm_kernel<<<gW, TB>>>(0, h, nullptr, N);
    spmm_kernel<<<gW, TB>>>(1, nullptr, nullptr, N);
    spmm_kernel<<<gW, TB>>>(2, nullptr, (float*)d_out, N);
}